// round 1
// baseline (speedup 1.0000x reference)
#include <cuda_runtime.h>
#include <cstdint>

#define PI_F 3.14159265358979323846f

// ---------------- scratch (device globals; no runtime allocation) ----------------
__device__ float2 g_spec[256u * 256u * 129u];      // [img=b*32+ch][row][k] spectrum
__device__ float  g_x1[8u * 256u * 256u * 32u];    // [pix][32] local-mixer out
__device__ float  g_x2[256u * 256u * 256u];        // [img][row][w] global-mixer out

__device__ __forceinline__ float2 cmulf(float2 a, float2 b) {
    return make_float2(a.x * b.x - a.y * b.y, a.x * b.y + a.y * b.x);
}

// ---------------- local mixer: window attention ----------------
// one block = one 8x8 window, 256 threads
__global__ __launch_bounds__(256) void attn_kernel(
    const float* __restrict__ x, const float* __restrict__ wqkv,
    const float* __restrict__ bqkv, const float* __restrict__ pos)
{
    __shared__ float xw[64][33];
    __shared__ float wq[96][33];
    __shared__ float bq[96];
    __shared__ float qs[64][33];
    __shared__ float ks[64][33];
    __shared__ float vs[64][33];

    int t = threadIdx.x;
    int wid = blockIdx.x;               // 0..8191
    int b   = wid >> 10;
    int hb  = (wid >> 5) & 31;
    int wb  = wid & 31;

    // load window x1 (channels 0..31): 64 tokens x 32 floats, float4
    {
        const float4* xv = (const float4*)x;
        #pragma unroll
        for (int e = 0; e < 2; e++) {
            int l = t + e * 256;        // 0..511
            int n = l >> 3;             // token
            int q4 = l & 7;             // float4 chunk
            int i = n >> 3, j = n & 7;
            size_t pix = ((size_t)(b * 256 + hb * 8 + i) * 256) + (wb * 8 + j);
            float4 v = xv[pix * 16 + q4];
            xw[n][q4 * 4 + 0] = v.x; xw[n][q4 * 4 + 1] = v.y;
            xw[n][q4 * 4 + 2] = v.z; xw[n][q4 * 4 + 3] = v.w;
        }
        #pragma unroll
        for (int e = 0; e < 12; e++) {
            int l = t + e * 256;        // 0..3071
            wq[l >> 5][l & 31] = wqkv[l];
        }
        if (t < 96) bq[t] = bqkv[t];
    }
    __syncthreads();

    // qkv = xw @ wqkv^T + bq ; thread = (token, 24 outputs)
    {
        int i  = t >> 2;
        int d0 = (t & 3) * 24;
        float xr[32];
        #pragma unroll
        for (int c = 0; c < 32; c++) xr[c] = xw[i][c];
        #pragma unroll
        for (int dd = 0; dd < 24; dd++) {
            int d = d0 + dd;
            float acc = bq[d];
            #pragma unroll
            for (int c = 0; c < 32; c++) acc += xr[c] * wq[d][c];
            if (d < 32)      qs[i][d]      = acc * 0.35355339059327373f; // hc^-0.5
            else if (d < 64) ks[i][d - 32] = acc;
            else             vs[i][d - 64] = acc;
        }
    }
    __syncthreads();

    // attention: thread = (head, query row)
    {
        int head = t >> 6;
        int i    = t & 63;
        float q8[8];
        #pragma unroll
        for (int c = 0; c < 8; c++) q8[c] = qs[i][head * 8 + c];
        const float* pp = pos + ((head * 64) + i) * 64;
        float sim[64];
        float m = -1e30f;
        #pragma unroll
        for (int j = 0; j < 64; j++) {
            float s = pp[j];
            #pragma unroll
            for (int c = 0; c < 8; c++) s += q8[c] * ks[j][head * 8 + c];
            sim[j] = s;
            m = fmaxf(m, s);
        }
        float sum = 0.f;
        #pragma unroll
        for (int j = 0; j < 64; j++) {
            float e = __expf(sim[j] - m);
            sim[j] = e; sum += e;
        }
        float inv = 1.f / sum;
        float o[8] = {0, 0, 0, 0, 0, 0, 0, 0};
        #pragma unroll
        for (int j = 0; j < 64; j++) {
            float p = sim[j];
            #pragma unroll
            for (int c = 0; c < 8; c++) o[c] += p * vs[j][head * 8 + c];
        }
        int i_r = i >> 3, j_c = i & 7;
        size_t pix = ((size_t)(b * 256 + hb * 8 + i_r) * 256) + (wb * 8 + j_c);
        float4* op = (float4*)(g_x1 + pix * 32 + head * 8);
        op[0] = make_float4(o[0] * inv, o[1] * inv, o[2] * inv, o[3] * inv);
        op[1] = make_float4(o[4] * inv, o[5] * inv, o[6] * inv, o[7] * inv);
    }
}

// ---------------- 8 parallel 256-pt Stockham radix-2 FFTs in smem ----------------
// all 256 threads of the block must call. Returns pointer holding the result (== bufA).
template <int SIGN>
__device__ __forceinline__ float2* fft8x256(float2* bufA, float2* bufB, int t)
{
    float2* in = bufA; float2* out = bufB;
    #pragma unroll
    for (int Ns = 1; Ns < 256; Ns <<= 1) {
        float fac = (float)SIGN * PI_F / (float)Ns;
        #pragma unroll
        for (int s = 0; s < 4; s++) {
            int m = t + s * 256;           // 0..1023 butterflies
            int f = m >> 7;                // which FFT
            int j = m & 127;
            float2 v0 = in[f * 256 + j];
            float2 v1 = in[f * 256 + j + 128];
            int r = j & (Ns - 1);
            float ang = fac * (float)r;
            float sn, cs; __sincosf(ang, &sn, &cs);
            float2 tw = cmulf(v1, make_float2(cs, sn));
            int idxD = ((j - r) << 1) + r; // (j/Ns)*2Ns + r
            out[f * 256 + idxD]      = make_float2(v0.x + tw.x, v0.y + tw.y);
            out[f * 256 + idxD + Ns] = make_float2(v0.x - tw.x, v0.y - tw.y);
        }
        __syncthreads();
        float2* tmp = in; in = out; out = tmp;
    }
    return in;  // after 8 stages this is bufA again
}

// ---------------- forward row rFFT (along w) ----------------
// block = (b, row, channel-group of 8); 8192 blocks, 256 threads
__global__ __launch_bounds__(256) void rowfft_kernel(const float* __restrict__ x)
{
    __shared__ float2 bufA[8 * 256];
    __shared__ float2 bufB[8 * 256];
    int t  = threadIdx.x;
    int bx = blockIdx.x;
    int b   = bx >> 10;
    int row = (bx >> 2) & 255;
    int g   = bx & 3;

    const float* xp = x + ((size_t)(b * 256 + row) * 256) * 64 + 32 + g * 8;
    #pragma unroll
    for (int e = 0; e < 8; e++) {
        int l = t + e * 256;        // 0..2047
        int w = l >> 3;
        int f = l & 7;
        bufA[f * 256 + w] = make_float2(xp[(size_t)w * 64 + f], 0.f);
    }
    __syncthreads();

    float2* res = fft8x256<-1>(bufA, bufB, t);

    int img0 = b * 32 + g * 8;
    #pragma unroll
    for (int f = 0; f < 8; f++) {
        if (t < 129)
            g_spec[((size_t)(img0 + f) * 256 + row) * 129 + t] = res[f * 256 + t];
    }
}

// ---------------- column FFT (along h) + amp/phase transform + column IFFT ------
// block = (k-group of 8, img); grid (17, 256), 256 threads
__global__ __launch_bounds__(256) void coltrans_kernel(
    const float* __restrict__ amp_w, const float* __restrict__ amp_b,
    const float* __restrict__ pha_w, const float* __restrict__ pha_b)
{
    __shared__ float2 bufA[8 * 256];
    __shared__ float2 bufB[8 * 256];
    int t   = threadIdx.x;
    int img = blockIdx.y;
    int k0  = blockIdx.x * 8;
    int ch  = img & 31;

    float aw = amp_w[ch], ab = amp_b[ch], pw = pha_w[ch], pb = pha_b[ch];

    size_t base = (size_t)img * 256 * 129;
    #pragma unroll
    for (int e = 0; e < 8; e++) {
        int l = t + e * 256;
        int row = l >> 3;
        int kk  = l & 7;
        int k   = k0 + kk;
        float2 v = make_float2(0.f, 0.f);
        if (k < 129) v = g_spec[base + (size_t)row * 129 + k];
        bufA[kk * 256 + row] = v;
    }
    __syncthreads();

    float2* mid = fft8x256<-1>(bufA, bufB, t);   // forward along h

    // elementwise amp/phase affine + reconstruction (+ reference epsilons)
    #pragma unroll
    for (int e = 0; e < 8; e++) {
        int idx = t + e * 256;
        float2 v = mid[idx];
        float amp = sqrtf(v.x * v.x + v.y * v.y);
        float pha = atan2f(v.y, v.x);
        float af = amp * aw + ab;
        float pf = pha * pw + pb;
        float sn, cs; __sincosf(pf, &sn, &cs);
        mid[idx] = make_float2(af * cs + 2e-8f, af * sn + 1e-8f);
    }
    __syncthreads();

    float2* res = fft8x256<1>(bufA, bufB, t);    // inverse along h (unscaled)

    #pragma unroll
    for (int e = 0; e < 8; e++) {
        int l = t + e * 256;
        int row = l >> 3;
        int kk  = l & 7;
        int k   = k0 + kk;
        if (k < 129) g_spec[base + (size_t)row * 129 + k] = res[kk * 256 + row];
    }
}

// ---------------- inverse row irFFT (along w) + abs ----------------
// block = (img, row-group of 8); 8192 blocks, 256 threads
__global__ __launch_bounds__(256) void rowifft_kernel()
{
    __shared__ float2 bufA[8 * 256];
    __shared__ float2 bufB[8 * 256];
    int t  = threadIdx.x;
    int bx = blockIdx.x;
    int img  = bx >> 5;
    int row0 = (bx & 31) * 8;

    size_t base = ((size_t)img * 256 + row0) * 129;
    #pragma unroll
    for (int f = 0; f < 8; f++) {
        if (t < 129) bufA[f * 256 + t] = g_spec[base + (size_t)f * 129 + t];
    }
    __syncthreads();
    // Hermitian mirror: X[256-k] = conj(X[k]), k = 1..127
    #pragma unroll
    for (int f = 0; f < 8; f++) {
        if (t >= 1 && t < 128) {
            float2 v = bufA[f * 256 + 128 - t];
            bufA[f * 256 + 128 + t] = make_float2(v.x, -v.y);
        }
    }
    __syncthreads();

    float2* res = fft8x256<1>(bufA, bufB, t);

    #pragma unroll
    for (int e = 0; e < 8; e++) {
        int l = t + e * 256;
        int f = l >> 8;
        int n = l & 255;
        float val = res[f * 256 + n].x * (1.f / 65536.f);  // 1/(256*256) backward norm
        g_x2[((size_t)img * 256 + row0 + f) * 256 + n] = fabsf(val);
    }
}

// ---------------- projection: out = [x1|x2] @ proj_w^T + proj_b ----------------
// block = 64 pixels, 64 threads; thread = 4 pixels x 16 output channels
__global__ __launch_bounds__(64) void proj_kernel(
    const float* __restrict__ pw, const float* __restrict__ pbias,
    float* __restrict__ out)
{
    __shared__ float Ws[64 * 65];
    __shared__ float x1s[32 * 65];   // [c][pi]
    __shared__ float x2s[32 * 65];   // [c][pi]
    int t  = threadIdx.x;
    int p0 = blockIdx.x * 64;
    int b    = p0 >> 16;
    int rem0 = p0 & 65535;

    #pragma unroll
    for (int e = 0; e < 64; e++) {
        int l = t + e * 64;                  // 0..4095
        Ws[(l >> 6) * 65 + (l & 63)] = pw[l];
    }
    #pragma unroll
    for (int e = 0; e < 32; e++) {
        int l = t + e * 64;                  // 0..2047
        int pi = l >> 5, c = l & 31;
        x1s[c * 65 + pi] = g_x1[(size_t)p0 * 32 + l];
    }
    {
        size_t xb = (size_t)b * 2097152 + rem0;
        #pragma unroll
        for (int e = 0; e < 32; e++) {
            int l = t + e * 64;
            int pi = l & 63, c = l >> 6;
            x2s[c * 65 + pi] = g_x2[xb + (size_t)c * 65536 + pi];
        }
    }
    __syncthreads();

    int pg    = t >> 2;            // pixel group: pixels pg*4 .. pg*4+3
    int dbase = (t & 3) << 4;      // 0,16,32,48
    float acc[4][16];
    #pragma unroll
    for (int p = 0; p < 4; p++)
        #pragma unroll
        for (int i = 0; i < 16; i++) acc[p][i] = pbias[dbase + i];

    #pragma unroll
    for (int c = 0; c < 32; c++) {
        float a[4], b2[4];
        #pragma unroll
        for (int p = 0; p < 4; p++) {
            a[p]  = x1s[c * 65 + pg * 4 + p];
            b2[p] = x2s[c * 65 + pg * 4 + p];
        }
        #pragma unroll
        for (int i = 0; i < 16; i++) {
            float w1 = Ws[(dbase + i) * 65 + c];
            float w2 = Ws[(dbase + i) * 65 + 32 + c];
            #pragma unroll
            for (int p = 0; p < 4; p++)
                acc[p][i] += a[p] * w1 + b2[p] * w2;
        }
    }
    #pragma unroll
    for (int p = 0; p < 4; p++) {
        float4* op = (float4*)(out + (size_t)(p0 + pg * 4 + p) * 64 + dbase);
        op[0] = make_float4(acc[p][0],  acc[p][1],  acc[p][2],  acc[p][3]);
        op[1] = make_float4(acc[p][4],  acc[p][5],  acc[p][6],  acc[p][7]);
        op[2] = make_float4(acc[p][8],  acc[p][9],  acc[p][10], acc[p][11]);
        op[3] = make_float4(acc[p][12], acc[p][13], acc[p][14], acc[p][15]);
    }
}

// ---------------- launch ----------------
extern "C" void kernel_launch(void* const* d_in, const int* in_sizes, int n_in,
                              void* d_out, int out_size)
{
    const float* x      = (const float*)d_in[0];
    const float* w_qkv  = (const float*)d_in[1];
    const float* b_qkv  = (const float*)d_in[2];
    const float* pos    = (const float*)d_in[3];
    const float* amp_w  = (const float*)d_in[4];
    const float* amp_b  = (const float*)d_in[5];
    const float* pha_w  = (const float*)d_in[6];
    const float* pha_b  = (const float*)d_in[7];
    const float* proj_w = (const float*)d_in[8];
    const float* proj_b = (const float*)d_in[9];
    float* out = (float*)d_out;

    attn_kernel<<<8192, 256>>>(x, w_qkv, b_qkv, pos);
    rowfft_kernel<<<8192, 256>>>(x);
    coltrans_kernel<<<dim3(17, 256), 256>>>(amp_w, amp_b, pha_w, pha_b);
    rowifft_kernel<<<8192, 256>>>();
    proj_kernel<<<8192, 64>>>(proj_w, proj_b, out);
}

// round 2
// speedup vs baseline: 1.4764x; 1.4764x over previous
#include <cuda_runtime.h>
#include <cstdint>

#define PI_F 3.14159265358979323846f
typedef unsigned long long u64;

// ---------------- scratch (device globals; no runtime allocation) ----------------
__device__ float2 g_spec[256u * 256u * 129u];      // [img=b*32+ch][row][k] spectrum
__device__ float  g_x1[8u * 256u * 256u * 32u];    // [pix][32] local-mixer out
__device__ float  g_x2[256u * 256u * 256u];        // [img][row][w] global-mixer out
__device__ float  g_posT[4 * 64 * 64];             // pos transposed: [h][j][i]

// ---------------- helpers ----------------
__device__ __forceinline__ u64 fma2(u64 a, u64 b, u64 c) {
    u64 d; asm("fma.rn.f32x2 %0, %1, %2, %3;" : "=l"(d) : "l"(a), "l"(b), "l"(c)); return d;
}
__device__ __forceinline__ u64 pack2(float lo, float hi) {
    u64 r; asm("mov.b64 %0, {%1, %2};" : "=l"(r) : "f"(lo), "f"(hi)); return r;
}
__device__ __forceinline__ float2 unpk(u64 v) {
    float2 r; asm("mov.b64 {%0, %1}, %2;" : "=f"(r.x), "=f"(r.y) : "l"(v)); return r;
}
__device__ __forceinline__ float2 cmulf(float2 a, float2 b) {
    return make_float2(a.x * b.x - a.y * b.y, a.x * b.y + a.y * b.x);
}

// ---------------- pos transpose (tiny, once per launch) ----------------
__global__ __launch_bounds__(256) void transpose_pos_kernel(const float* __restrict__ pos)
{
    int idx = blockIdx.x * 256 + threadIdx.x;      // 16384 elements
    int h = idx >> 12;
    int j = (idx >> 6) & 63;
    int i = idx & 63;
    g_posT[idx] = pos[((h * 64) + i) * 64 + j];
}

// ---------------- local mixer: window attention ----------------
// one block = one 8x8 window, 256 threads
__global__ __launch_bounds__(256) void attn_kernel(
    const float* __restrict__ x, const float* __restrict__ wqkv,
    const float* __restrict__ bqkv)
{
    __shared__ float xw[64][36];   // float4-store friendly (36*4 = 144B rows)
    __shared__ float wq[96][34];   // u64-load friendly (even stride)
    __shared__ float bq[96];
    __shared__ float qs[64][34];
    __shared__ float ks[64][34];
    __shared__ float vs[64][34];

    int t = threadIdx.x;
    int wid = blockIdx.x;               // 0..8191
    int b   = wid >> 10;
    int hb  = (wid >> 5) & 31;
    int wb  = wid & 31;

    // load window x1 (channels 0..31): 64 tokens x 32 floats, float4
    {
        const float4* xv = (const float4*)x;
        #pragma unroll
        for (int e = 0; e < 2; e++) {
            int l = t + e * 256;        // 0..511
            int n = l >> 3;             // token
            int q4 = l & 7;             // float4 chunk
            int i = n >> 3, j = n & 7;
            size_t pix = ((size_t)(b * 256 + hb * 8 + i) * 256) + (wb * 8 + j);
            *(float4*)&xw[n][q4 * 4] = xv[pix * 16 + q4];
        }
        #pragma unroll
        for (int e = 0; e < 12; e++) {
            int l = t + e * 256;        // 0..3071
            wq[l >> 5][l & 31] = wqkv[l];
        }
        if (t < 96) bq[t] = bqkv[t];
    }
    __syncthreads();

    // qkv = xw @ wqkv^T + bq ; thread = (token i, quarter qq), 24 outputs, f32x2 math
    {
        int i  = t >> 2;
        int qq = t & 3;
        u64 xr[16];
        #pragma unroll
        for (int c = 0; c < 16; c++) xr[c] = *(const u64*)&xw[i][2 * c];
        #pragma unroll
        for (int kind = 0; kind < 3; kind++) {
            #pragma unroll
            for (int dd = 0; dd < 8; dd++) {
                int dc = qq * 8 + dd;
                int d  = kind * 32 + dc;
                u64 a2 = 0ull;
                #pragma unroll
                for (int c = 0; c < 16; c++)
                    a2 = fma2(xr[c], *(const u64*)&wq[d][2 * c], a2);
                float2 p = unpk(a2);
                float acc = p.x + p.y + bq[d];
                if (kind == 0)      qs[i][dc] = acc * 0.35355339059327373f; // hc^-0.5
                else if (kind == 1) ks[i][dc] = acc;
                else                vs[i][dc] = acc;
            }
        }
    }
    __syncthreads();

    // attention: thread = (head, query row), f32x2 math, coalesced posT reads
    {
        int head = t >> 6;
        int i    = t & 63;
        const float* pT = g_posT + head * 4096 + i;   // pT[j*64] coalesced across lanes
        u64 q2[4];
        #pragma unroll
        for (int c = 0; c < 4; c++) q2[c] = *(const u64*)&qs[i][head * 8 + 2 * c];

        float sim[64];
        float m = -1e30f;
        #pragma unroll
        for (int j = 0; j < 64; j++) {
            u64 a2 = 0ull;
            #pragma unroll
            for (int c = 0; c < 4; c++)
                a2 = fma2(q2[c], *(const u64*)&ks[j][head * 8 + 2 * c], a2);
            float2 p = unpk(a2);
            float s = p.x + p.y + pT[j * 64];
            sim[j] = s;
            m = fmaxf(m, s);
        }
        float sum = 0.f;
        #pragma unroll
        for (int j = 0; j < 64; j++) {
            float e = __expf(sim[j] - m);
            sim[j] = e; sum += e;
        }
        float inv = 1.f / sum;
        u64 o2[4] = {0ull, 0ull, 0ull, 0ull};
        #pragma unroll
        for (int j = 0; j < 64; j++) {
            u64 pb = pack2(sim[j], sim[j]);
            #pragma unroll
            for (int c = 0; c < 4; c++)
                o2[c] = fma2(pb, *(const u64*)&vs[j][head * 8 + 2 * c], o2[c]);
        }
        float2 r0 = unpk(o2[0]), r1 = unpk(o2[1]), r2 = unpk(o2[2]), r3 = unpk(o2[3]);
        int ir = i >> 3, jc = i & 7;
        size_t pix = ((size_t)(b * 256 + hb * 8 + ir) * 256) + (wb * 8 + jc);
        float4* op = (float4*)(g_x1 + pix * 32 + head * 8);
        op[0] = make_float4(r0.x * inv, r0.y * inv, r1.x * inv, r1.y * inv);
        op[1] = make_float4(r2.x * inv, r2.y * inv, r3.x * inv, r3.y * inv);
    }
}

// ---------------- 8 parallel 256-pt Stockham radix-4 FFTs in smem ----------------
// all 256 threads must call. 4 stages -> result back in bufA.
template <int SIGN>
__device__ __forceinline__ float2* fft8x256_r4(float2* bufA, float2* bufB, int t)
{
    float2* in = bufA; float2* out = bufB;
    #pragma unroll
    for (int Ns = 1; Ns < 256; Ns <<= 2) {
        float fac = (float)SIGN * (PI_F * 0.5f) / (float)Ns;  // 2*pi/(4*Ns)
        #pragma unroll
        for (int s = 0; s < 2; s++) {
            int m = t + s * 256;           // 0..511 butterflies
            int f = m >> 6;                // which FFT
            int j = m & 63;
            const float2* ip = in + f * 256;
            float2 v0 = ip[j];
            float2 v1 = ip[j + 64];
            float2 v2 = ip[j + 128];
            float2 v3 = ip[j + 192];
            int r = j & (Ns - 1);
            float ang = fac * (float)r;
            float sn, cs; __sincosf(ang, &sn, &cs);
            float2 w1 = make_float2(cs, sn);
            float2 w2 = cmulf(w1, w1);
            float2 w3 = cmulf(w2, w1);
            v1 = cmulf(v1, w1);
            v2 = cmulf(v2, w2);
            v3 = cmulf(v3, w3);
            float2 t0 = make_float2(v0.x + v2.x, v0.y + v2.y);
            float2 t1 = make_float2(v0.x - v2.x, v0.y - v2.y);
            float2 t2 = make_float2(v1.x + v3.x, v1.y + v3.y);
            float2 t3 = make_float2(v1.x - v3.x, v1.y - v3.y);
            // X1 = t1 + SIGN*i*t3 ; X3 = t1 - SIGN*i*t3
            float sx = (float)SIGN * t3.x;
            float sy = (float)SIGN * t3.y;
            int idxD = ((j - r) << 2) + r;   // (j/Ns)*4Ns + r
            float2* op = out + f * 256;
            op[idxD]          = make_float2(t0.x + t2.x, t0.y + t2.y);
            op[idxD + Ns]     = make_float2(t1.x - sy,   t1.y + sx);
            op[idxD + 2 * Ns] = make_float2(t0.x - t2.x, t0.y - t2.y);
            op[idxD + 3 * Ns] = make_float2(t1.x + sy,   t1.y - sx);
        }
        __syncthreads();
        float2* tmp = in; in = out; out = tmp;
    }
    return in;  // 4 stages -> bufA
}

// ---------------- forward row rFFT (along w) ----------------
// block = (b, row, channel-group of 8); 8192 blocks, 256 threads
__global__ __launch_bounds__(256) void rowfft_kernel(const float* __restrict__ x)
{
    __shared__ float2 bufA[8 * 256];
    __shared__ float2 bufB[8 * 256];
    int t  = threadIdx.x;
    int bx = blockIdx.x;
    int b   = bx >> 10;
    int row = (bx >> 2) & 255;
    int g   = bx & 3;

    const float* xp = x + ((size_t)(b * 256 + row) * 256) * 64 + 32 + g * 8;
    #pragma unroll
    for (int e = 0; e < 8; e++) {
        int l = t + e * 256;        // 0..2047
        int w = l >> 3;
        int f = l & 7;
        bufA[f * 256 + w] = make_float2(xp[(size_t)w * 64 + f], 0.f);
    }
    __syncthreads();

    float2* res = fft8x256_r4<-1>(bufA, bufB, t);

    int img0 = b * 32 + g * 8;
    #pragma unroll
    for (int f = 0; f < 8; f++) {
        if (t < 129)
            g_spec[((size_t)(img0 + f) * 256 + row) * 129 + t] = res[f * 256 + t];
    }
}

// ---------------- column FFT (along h) + amp/phase transform + column IFFT ------
// block = (k-group of 8, img); grid (17, 256), 256 threads
__global__ __launch_bounds__(256) void coltrans_kernel(
    const float* __restrict__ amp_w, const float* __restrict__ amp_b,
    const float* __restrict__ pha_w, const float* __restrict__ pha_b)
{
    __shared__ float2 bufA[8 * 256];
    __shared__ float2 bufB[8 * 256];
    int t   = threadIdx.x;
    int img = blockIdx.y;
    int k0  = blockIdx.x * 8;
    int ch  = img & 31;

    float aw = amp_w[ch], ab = amp_b[ch], pw = pha_w[ch], pb = pha_b[ch];

    size_t base = (size_t)img * 256 * 129;
    #pragma unroll
    for (int e = 0; e < 8; e++) {
        int l = t + e * 256;
        int row = l >> 3;
        int kk  = l & 7;
        int k   = k0 + kk;
        float2 v = make_float2(0.f, 0.f);
        if (k < 129) v = g_spec[base + (size_t)row * 129 + k];
        bufA[kk * 256 + row] = v;
    }
    __syncthreads();

    float2* mid = fft8x256_r4<-1>(bufA, bufB, t);   // forward along h

    // elementwise amp/phase affine + reconstruction (+ reference epsilons)
    #pragma unroll
    for (int e = 0; e < 8; e++) {
        int idx = t + e * 256;
        float2 v = mid[idx];
        float amp = sqrtf(v.x * v.x + v.y * v.y);
        float pha = atan2f(v.y, v.x);
        float af = amp * aw + ab;
        float pf = pha * pw + pb;
        float sn, cs; __sincosf(pf, &sn, &cs);
        mid[idx] = make_float2(af * cs + 2e-8f, af * sn + 1e-8f);
    }
    __syncthreads();

    float2* res = fft8x256_r4<1>(bufA, bufB, t);    // inverse along h (unscaled)

    #pragma unroll
    for (int e = 0; e < 8; e++) {
        int l = t + e * 256;
        int row = l >> 3;
        int kk  = l & 7;
        int k   = k0 + kk;
        if (k < 129) g_spec[base + (size_t)row * 129 + k] = res[kk * 256 + row];
    }
}

// ---------------- inverse row irFFT (along w) + abs ----------------
// block = (img, row-group of 8); 8192 blocks, 256 threads
__global__ __launch_bounds__(256) void rowifft_kernel()
{
    __shared__ float2 bufA[8 * 256];
    __shared__ float2 bufB[8 * 256];
    int t  = threadIdx.x;
    int bx = blockIdx.x;
    int img  = bx >> 5;
    int row0 = (bx & 31) * 8;

    size_t base = ((size_t)img * 256 + row0) * 129;
    #pragma unroll
    for (int f = 0; f < 8; f++) {
        if (t < 129) bufA[f * 256 + t] = g_spec[base + (size_t)f * 129 + t];
    }
    __syncthreads();
    // Hermitian mirror: X[256-k] = conj(X[k]), k = 1..127
    #pragma unroll
    for (int f = 0; f < 8; f++) {
        if (t >= 1 && t < 128) {
            float2 v = bufA[f * 256 + 128 - t];
            bufA[f * 256 + 128 + t] = make_float2(v.x, -v.y);
        }
    }
    __syncthreads();

    float2* res = fft8x256_r4<1>(bufA, bufB, t);

    #pragma unroll
    for (int e = 0; e < 8; e++) {
        int l = t + e * 256;
        int f = l >> 8;
        int n = l & 255;
        float val = res[f * 256 + n].x * (1.f / 65536.f);  // 1/(256*256) backward norm
        g_x2[((size_t)img * 256 + row0 + f) * 256 + n] = fabsf(val);
    }
}

// ---------------- projection: out = [x1|x2] @ proj_w^T + proj_b ----------------
// block = 64 pixels, 64 threads; thread = 4 pixels x 16 output channels, f32x2
__global__ __launch_bounds__(64) void proj_kernel(
    const float* __restrict__ pw, const float* __restrict__ pbias,
    float* __restrict__ out)
{
    __shared__ float WsT[64][68];    // transposed weights: [in c][out d]
    __shared__ float x1s[32][68];    // [c][pi]
    __shared__ float x2s[32][68];    // [c][pi]
    int t  = threadIdx.x;
    int p0 = blockIdx.x * 64;
    int b    = p0 >> 16;
    int rem0 = p0 & 65535;

    #pragma unroll
    for (int e = 0; e < 64; e++) WsT[t][e] = pw[e * 64 + t];     // coalesced reads
    #pragma unroll
    for (int e = 0; e < 32; e++) {
        int l = e * 64 + t;                  // 0..2047, coalesced read of g_x1
        x1s[l & 31][l >> 5] = g_x1[(size_t)p0 * 32 + l];
    }
    {
        size_t xb = (size_t)b * 2097152 + rem0;
        #pragma unroll
        for (int e = 0; e < 32; e++)
            x2s[e][t] = g_x2[xb + (size_t)e * 65536 + t];        // coalesced per channel
    }
    __syncthreads();

    int pg    = t >> 2;            // pixel group: pixels pg*4 .. pg*4+3
    int dbase = (t & 3) << 4;      // 0,16,32,48
    u64 acc[4][8];                 // [pixel][d-pair]
    #pragma unroll
    for (int k = 0; k < 8; k++) {
        u64 bp = *(const u64*)&pbias[dbase + 2 * k];
        #pragma unroll
        for (int p = 0; p < 4; p++) acc[p][k] = bp;
    }

    #pragma unroll
    for (int c = 0; c < 32; c++) {
        float4 a  = *(const float4*)&x1s[c][pg * 4];
        float4 b2 = *(const float4*)&x2s[c][pg * 4];
        u64 ax[4] = {pack2(a.x, a.x),  pack2(a.y, a.y),  pack2(a.z, a.z),  pack2(a.w, a.w)};
        u64 bx[4] = {pack2(b2.x, b2.x), pack2(b2.y, b2.y), pack2(b2.z, b2.z), pack2(b2.w, b2.w)};
        #pragma unroll
        for (int k = 0; k < 8; k++) {
            u64 w1 = *(const u64*)&WsT[c][dbase + 2 * k];
            u64 w2 = *(const u64*)&WsT[32 + c][dbase + 2 * k];
            #pragma unroll
            for (int p = 0; p < 4; p++) {
                acc[p][k] = fma2(ax[p], w1, acc[p][k]);
                acc[p][k] = fma2(bx[p], w2, acc[p][k]);
            }
        }
    }

    #pragma unroll
    for (int p = 0; p < 4; p++) {
        float* o = out + (size_t)(p0 + pg * 4 + p) * 64 + dbase;
        #pragma unroll
        for (int k = 0; k < 4; k++) {
            float2 lo = unpk(acc[p][2 * k]);
            float2 hi = unpk(acc[p][2 * k + 1]);
            *(float4*)&o[4 * k] = make_float4(lo.x, lo.y, hi.x, hi.y);
        }
    }
}

// ---------------- launch ----------------
extern "C" void kernel_launch(void* const* d_in, const int* in_sizes, int n_in,
                              void* d_out, int out_size)
{
    const float* x      = (const float*)d_in[0];
    const float* w_qkv  = (const float*)d_in[1];
    const float* b_qkv  = (const float*)d_in[2];
    const float* pos    = (const float*)d_in[3];
    const float* amp_w  = (const float*)d_in[4];
    const float* amp_b  = (const float*)d_in[5];
    const float* pha_w  = (const float*)d_in[6];
    const float* pha_b  = (const float*)d_in[7];
    const float* proj_w = (const float*)d_in[8];
    const float* proj_b = (const float*)d_in[9];
    float* out = (float*)d_out;

    transpose_pos_kernel<<<64, 256>>>(pos);
    attn_kernel<<<8192, 256>>>(x, w_qkv, b_qkv);
    rowfft_kernel<<<8192, 256>>>(x);
    coltrans_kernel<<<dim3(17, 256), 256>>>(amp_w, amp_b, pha_w, pha_b);
    rowifft_kernel<<<8192, 256>>>();
    proj_kernel<<<8192, 64>>>(proj_w, proj_b, out);
}

// round 4
// speedup vs baseline: 2.1942x; 1.4861x over previous
#include <cuda_runtime.h>
#include <cstdint>

#define PI_F 3.14159265358979323846f
typedef unsigned long long u64;

// ---------------- scratch (device globals; no runtime allocation) ----------------
__device__ float2 g_spec[256u * 256u * 129u];      // [img=b*32+ch][row][k] spectrum
__device__ float  g_x1[8u * 256u * 256u * 32u];    // [pix][32] local-mixer out
__device__ float  g_x2[256u * 256u * 256u];        // [img][row][w] global-mixer out
__device__ float  g_posT[4 * 64 * 64];             // pos transposed: [h][j][i]

// ---------------- helpers ----------------
__device__ __forceinline__ u64 fma2(u64 a, u64 b, u64 c) {
    u64 d; asm("fma.rn.f32x2 %0, %1, %2, %3;" : "=l"(d) : "l"(a), "l"(b), "l"(c)); return d;
}
__device__ __forceinline__ u64 pack2(float lo, float hi) {
    u64 r; asm("mov.b64 %0, {%1, %2};" : "=l"(r) : "f"(lo), "f"(hi)); return r;
}
__device__ __forceinline__ float2 unpk(u64 v) {
    float2 r; asm("mov.b64 {%0, %1}, %2;" : "=f"(r.x), "=f"(r.y) : "l"(v)); return r;
}
__device__ __forceinline__ float2 cmulf(float2 a, float2 b) {
    return make_float2(a.x * b.x - a.y * b.y, a.x * b.y + a.y * b.x);
}

// bank-conflict-killing swizzle for the FFT smem buffers (fixed bijection per FFT).
__device__ __forceinline__ int phy(int idx, int fx) {
    return idx ^ ((((idx) >> 4) & 3) * 5) ^ fx;
}
__device__ __forceinline__ int fxof(int f) {
    return ((f & 1) * 9) ^ (f & 2) ^ (f & 4);
}

// ---------------- pos transpose (tiny, once per launch) ----------------
__global__ __launch_bounds__(256) void transpose_pos_kernel(const float* __restrict__ pos)
{
    int idx = blockIdx.x * 256 + threadIdx.x;      // 16384 elements
    int h = idx >> 12;
    int j = (idx >> 6) & 63;
    int i = idx & 63;
    g_posT[idx] = pos[((h * 64) + i) * 64 + j];
}

// ---------------- local mixer: window attention ----------------
// one block = one 8x8 window, 256 threads. thread t -> (token i = t&63, head/quarter hq = t>>6)
__global__ __launch_bounds__(256) void attn_kernel(
    const float* __restrict__ x, const float* __restrict__ wqkv,
    const float* __restrict__ bqkv)
{
    __shared__ float xw[64][36];   // 144B rows, 16B aligned
    __shared__ float wq[96][36];
    __shared__ float bq[96];
    __shared__ float ks[64][36];
    __shared__ float vs[64][36];

    int t = threadIdx.x;
    int wid = blockIdx.x;               // 0..8191
    int b   = wid >> 10;
    int hb  = (wid >> 5) & 31;
    int wb  = wid & 31;

    // load window x1 (channels 0..31): 64 tokens x 32 floats, float4
    {
        const float4* xv = (const float4*)x;
        #pragma unroll
        for (int e = 0; e < 2; e++) {
            int l = t + e * 256;        // 0..511
            int n = l >> 3;             // token
            int q4 = l & 7;             // float4 chunk
            int i = n >> 3, j = n & 7;
            size_t pix = ((size_t)(b * 256 + hb * 8 + i) * 256) + (wb * 8 + j);
            *(float4*)&xw[n][q4 * 4] = xv[pix * 16 + q4];
        }
        #pragma unroll
        for (int e = 0; e < 12; e++) {
            int l = t + e * 256;        // 0..3071
            wq[l >> 5][l & 31] = wqkv[l];
        }
        if (t < 96) bq[t] = bqkv[t];
    }
    __syncthreads();

    int i  = t & 63;    // token
    int hq = t >> 6;    // head == qkv quarter for this thread

    // register-cache this token's row
    u64 xr[16];
    #pragma unroll
    for (int c = 0; c < 8; c++) {
        ulonglong2 v = *(const ulonglong2*)&xw[i][4 * c];
        xr[2 * c] = v.x; xr[2 * c + 1] = v.y;
    }

    // qkv for this thread's 8 channels of each of q,k,v.
    // Weight rows are UNIFORM across the warp (hq const per warp) -> broadcast LDS.128.
    u64 q2[4];
    #pragma unroll
    for (int kind = 0; kind < 3; kind++) {
        float o[8];
        #pragma unroll
        for (int dd = 0; dd < 8; dd++) {
            int d = kind * 32 + hq * 8 + dd;
            const float* wrow = &wq[d][0];
            u64 a0 = 0ull, a1 = 0ull;
            #pragma unroll
            for (int c = 0; c < 4; c++) {
                ulonglong2 w0 = *(const ulonglong2*)(wrow + 8 * c);        // floats 8c..8c+3
                ulonglong2 w1 = *(const ulonglong2*)(wrow + 8 * c + 4);    // floats 8c+4..8c+7
                a0 = fma2(xr[4 * c],     w0.x, a0);
                a1 = fma2(xr[4 * c + 1], w0.y, a1);
                a0 = fma2(xr[4 * c + 2], w1.x, a0);
                a1 = fma2(xr[4 * c + 3], w1.y, a1);
            }
            float2 p = unpk(a0), q = unpk(a1);
            o[dd] = p.x + p.y + q.x + q.y + bq[d];
        }
        if (kind == 0) {
            #pragma unroll
            for (int c = 0; c < 4; c++)
                q2[c] = pack2(o[2 * c]     * 0.35355339059327373f,
                              o[2 * c + 1] * 0.35355339059327373f);
        } else if (kind == 1) {
            *(float4*)&ks[i][hq * 8]     = make_float4(o[0], o[1], o[2], o[3]);
            *(float4*)&ks[i][hq * 8 + 4] = make_float4(o[4], o[5], o[6], o[7]);
        } else {
            *(float4*)&vs[i][hq * 8]     = make_float4(o[0], o[1], o[2], o[3]);
            *(float4*)&vs[i][hq * 8 + 4] = make_float4(o[4], o[5], o[6], o[7]);
        }
    }
    __syncthreads();

    // attention: thread = (head hq, query row i). K/V rows uniform per warp.
    {
        const float* pT = g_posT + hq * 4096 + i;   // pT[j*64] coalesced across lanes
        float sim[64];
        float m = -1e30f;
        #pragma unroll
        for (int j = 0; j < 64; j++) {
            ulonglong2 k0 = *(const ulonglong2*)&ks[j][hq * 8];
            ulonglong2 k1 = *(const ulonglong2*)&ks[j][hq * 8 + 4];
            u64 a = 0ull;
            a = fma2(q2[0], k0.x, a);
            a = fma2(q2[1], k0.y, a);
            a = fma2(q2[2], k1.x, a);
            a = fma2(q2[3], k1.y, a);
            float2 p = unpk(a);
            float s = p.x + p.y + pT[j * 64];
            sim[j] = s;
            m = fmaxf(m, s);
        }
        float sum = 0.f;
        #pragma unroll
        for (int j = 0; j < 64; j++) {
            float e = __expf(sim[j] - m);
            sim[j] = e; sum += e;
        }
        float inv = 1.f / sum;
        u64 o2[4] = {0ull, 0ull, 0ull, 0ull};
        #pragma unroll
        for (int j = 0; j < 64; j++) {
            ulonglong2 v0 = *(const ulonglong2*)&vs[j][hq * 8];
            ulonglong2 v1 = *(const ulonglong2*)&vs[j][hq * 8 + 4];
            u64 pb = pack2(sim[j], sim[j]);
            o2[0] = fma2(pb, v0.x, o2[0]);
            o2[1] = fma2(pb, v0.y, o2[1]);
            o2[2] = fma2(pb, v1.x, o2[2]);
            o2[3] = fma2(pb, v1.y, o2[3]);
        }
        float2 r0 = unpk(o2[0]), r1 = unpk(o2[1]), r2 = unpk(o2[2]), r3 = unpk(o2[3]);
        int ir = i >> 3, jc = i & 7;
        size_t pix = ((size_t)(b * 256 + hb * 8 + ir) * 256) + (wb * 8 + jc);
        float4* op = (float4*)(g_x1 + pix * 32 + hq * 8);
        op[0] = make_float4(r0.x * inv, r0.y * inv, r1.x * inv, r1.y * inv);
        op[1] = make_float4(r2.x * inv, r2.y * inv, r3.x * inv, r3.y * inv);
    }
}

// ---------------- 8 parallel 256-pt Stockham radix-4 FFTs in smem (swizzled) ----
// all 256 threads must call. 4 stages -> result back in bufA. All buffer indices
// are PHYSICAL (phy-swizzled); callers must use phy() too.
template <int SIGN>
__device__ __forceinline__ float2* fft8x256_r4(float2* bufA, float2* bufB, int t)
{
    float2* in = bufA; float2* out = bufB;
    #pragma unroll
    for (int Ns = 1; Ns < 256; Ns <<= 2) {
        float fac = (float)SIGN * (PI_F * 0.5f) / (float)Ns;  // 2*pi/(4*Ns)
        #pragma unroll
        for (int s = 0; s < 2; s++) {
            int m = t + s * 256;           // 0..511 butterflies
            int f = m >> 6;                // which FFT
            int fb = f * 256;
            int fx = fxof(f);
            int j = m & 63;
            float2 v0 = in[fb + phy(j,       fx)];
            float2 v1 = in[fb + phy(j + 64,  fx)];
            float2 v2 = in[fb + phy(j + 128, fx)];
            float2 v3 = in[fb + phy(j + 192, fx)];
            int r = j & (Ns - 1);
            float ang = fac * (float)r;
            float sn, cs; __sincosf(ang, &sn, &cs);
            float2 w1 = make_float2(cs, sn);
            float2 w2 = cmulf(w1, w1);
            float2 w3 = cmulf(w2, w1);
            v1 = cmulf(v1, w1);
            v2 = cmulf(v2, w2);
            v3 = cmulf(v3, w3);
            float2 t0 = make_float2(v0.x + v2.x, v0.y + v2.y);
            float2 t1 = make_float2(v0.x - v2.x, v0.y - v2.y);
            float2 t2 = make_float2(v1.x + v3.x, v1.y + v3.y);
            float2 t3 = make_float2(v1.x - v3.x, v1.y - v3.y);
            float sx = (float)SIGN * t3.x;
            float sy = (float)SIGN * t3.y;
            int idxD = ((j - r) << 2) + r;   // (j/Ns)*4Ns + r
            out[fb + phy(idxD,          fx)] = make_float2(t0.x + t2.x, t0.y + t2.y);
            out[fb + phy(idxD + Ns,     fx)] = make_float2(t1.x - sy,   t1.y + sx);
            out[fb + phy(idxD + 2 * Ns, fx)] = make_float2(t0.x - t2.x, t0.y - t2.y);
            out[fb + phy(idxD + 3 * Ns, fx)] = make_float2(t1.x + sy,   t1.y - sx);
        }
        __syncthreads();
        float2* tmp = in; in = out; out = tmp;
    }
    return in;  // 4 stages -> bufA
}

// ---------------- forward row rFFT (along w) ----------------
// block = (b, row, channel-group of 8); 8192 blocks, 256 threads
__global__ __launch_bounds__(256) void rowfft_kernel(const float* __restrict__ x)
{
    __shared__ float2 bufA[8 * 256];
    __shared__ float2 bufB[8 * 256];
    int t  = threadIdx.x;
    int bx = blockIdx.x;
    int b   = bx >> 10;
    int row = (bx >> 2) & 255;
    int g   = bx & 3;

    const float* xp = x + ((size_t)(b * 256 + row) * 256) * 64 + 32 + g * 8;
    #pragma unroll
    for (int e = 0; e < 8; e++) {
        int l = t + e * 256;        // 0..2047
        int w = l >> 3;
        int f = l & 7;
        bufA[f * 256 + phy(w, fxof(f))] = make_float2(xp[(size_t)w * 64 + f], 0.f);
    }
    __syncthreads();

    float2* res = fft8x256_r4<-1>(bufA, bufB, t);

    int img0 = b * 32 + g * 8;
    #pragma unroll
    for (int f = 0; f < 8; f++) {
        if (t < 129)
            g_spec[((size_t)(img0 + f) * 256 + row) * 129 + t] = res[f * 256 + phy(t, fxof(f))];
    }
}

// ---------------- column FFT (along h) + amp/phase transform + column IFFT ------
// block = (k-group of 8, img); grid (17, 256), 256 threads
__global__ __launch_bounds__(256) void coltrans_kernel(
    const float* __restrict__ amp_w, const float* __restrict__ amp_b,
    const float* __restrict__ pha_w, const float* __restrict__ pha_b)
{
    __shared__ float2 bufA[8 * 256];
    __shared__ float2 bufB[8 * 256];
    int t   = threadIdx.x;
    int img = blockIdx.y;
    int k0  = blockIdx.x * 8;
    int ch  = img & 31;

    float aw = amp_w[ch], ab = amp_b[ch], pw = pha_w[ch], pb = pha_b[ch];

    size_t base = (size_t)img * 256 * 129;
    #pragma unroll
    for (int e = 0; e < 8; e++) {
        int l = t + e * 256;
        int row = l >> 3;
        int kk  = l & 7;
        int k   = k0 + kk;
        float2 v = make_float2(0.f, 0.f);
        if (k < 129) v = g_spec[base + (size_t)row * 129 + k];
        bufA[kk * 256 + phy(row, fxof(kk))] = v;
    }
    __syncthreads();

    float2* mid = fft8x256_r4<-1>(bufA, bufB, t);   // forward along h

    // elementwise amp/phase affine (order-agnostic: operate on physical slots)
    #pragma unroll
    for (int e = 0; e < 8; e++) {
        int idx = t + e * 256;
        float2 v = mid[idx];
        float amp = sqrtf(v.x * v.x + v.y * v.y);
        float pha = atan2f(v.y, v.x);
        float af = amp * aw + ab;
        float pf = pha * pw + pb;
        float sn, cs; __sincosf(pf, &sn, &cs);
        mid[idx] = make_float2(af * cs + 2e-8f, af * sn + 1e-8f);
    }
    __syncthreads();

    float2* res = fft8x256_r4<1>(bufA, bufB, t);    // inverse along h (unscaled)

    #pragma unroll
    for (int e = 0; e < 8; e++) {
        int l = t + e * 256;
        int row = l >> 3;
        int kk  = l & 7;
        int k   = k0 + kk;
        if (k < 129) g_spec[base + (size_t)row * 129 + k] = res[kk * 256 + phy(row, fxof(kk))];
    }
}

// ---------------- inverse row irFFT (along w) + abs ----------------
// block = (img, row-group of 8); 8192 blocks, 256 threads
__global__ __launch_bounds__(256) void rowifft_kernel()
{
    __shared__ float2 bufA[8 * 256];
    __shared__ float2 bufB[8 * 256];
    int t  = threadIdx.x;
    int bx = blockIdx.x;
    int img  = bx >> 5;
    int row0 = (bx & 31) * 8;

    size_t base = ((size_t)img * 256 + row0) * 129;
    #pragma unroll
    for (int f = 0; f < 8; f++) {
        if (t < 129) bufA[f * 256 + phy(t, fxof(f))] = g_spec[base + (size_t)f * 129 + t];
    }
    __syncthreads();
    // Hermitian mirror: X[256-k] = conj(X[k]), k = 1..127
    #pragma unroll
    for (int f = 0; f < 8; f++) {
        if (t >= 1 && t < 128) {
            int fx = fxof(f);
            float2 v = bufA[f * 256 + phy(128 - t, fx)];
            bufA[f * 256 + phy(128 + t, fx)] = make_float2(v.x, -v.y);
        }
    }
    __syncthreads();

    float2* res = fft8x256_r4<1>(bufA, bufB, t);

    #pragma unroll
    for (int e = 0; e < 8; e++) {
        int l = t + e * 256;
        int f = l >> 8;
        int n = l & 255;
        float val = res[f * 256 + phy(n, fxof(f))].x * (1.f / 65536.f);
        g_x2[((size_t)img * 256 + row0 + f) * 256 + n] = fabsf(val);
    }
}

// ---------------- projection: out = [x1|x2] @ proj_w^T + proj_b ----------------
// block = 64 pixels, 64 threads; thread = 4 pixels x 16 output channels, f32x2
__global__ __launch_bounds__(64) void proj_kernel(
    const float* __restrict__ pw, const float* __restrict__ pbias,
    float* __restrict__ out)
{
    __shared__ float WsT[64][68];    // transposed weights: [in c][out d]
    __shared__ float x1s[32][68];    // [c][pi]
    __shared__ float x2s[32][68];    // [c][pi]
    int t  = threadIdx.x;
    int p0 = blockIdx.x * 64;
    int b    = p0 >> 16;
    int rem0 = p0 & 65535;

    #pragma unroll
    for (int e = 0; e < 64; e++) WsT[t][e] = pw[e * 64 + t];     // coalesced reads
    #pragma unroll
    for (int e = 0; e < 32; e++) {
        int l = e * 64 + t;                  // 0..2047, coalesced read of g_x1
        x1s[l & 31][l >> 5] = g_x1[(size_t)p0 * 32 + l];
    }
    {
        size_t xb = (size_t)b * 2097152 + rem0;
        #pragma unroll
        for (int e = 0; e < 32; e++)
            x2s[e][t] = g_x2[xb + (size_t)e * 65536 + t];        // coalesced per channel
    }
    __syncthreads();

    int pg    = t >> 2;            // pixel group: pixels pg*4 .. pg*4+3
    int dbase = (t & 3) << 4;      // 0,16,32,48
    u64 acc[4][8];                 // [pixel][d-pair]
    #pragma unroll
    for (int k = 0; k < 8; k++) {
        u64 bp = *(const u64*)&pbias[dbase + 2 * k];
        #pragma unroll
        for (int p = 0; p < 4; p++) acc[p][k] = bp;
    }

    #pragma unroll
    for (int c = 0; c < 32; c++) {
        float4 a  = *(const float4*)&x1s[c][pg * 4];
        float4 b2 = *(const float4*)&x2s[c][pg * 4];
        u64 ax[4] = {pack2(a.x, a.x),   pack2(a.y, a.y),   pack2(a.z, a.z),   pack2(a.w, a.w)};
        u64 bx[4] = {pack2(b2.x, b2.x), pack2(b2.y, b2.y), pack2(b2.z, b2.z), pack2(b2.w, b2.w)};
        // weights via broadcast LDS.128 (uniform within lane-quad)
        ulonglong2 wA0 = *(const ulonglong2*)&WsT[c][dbase];
        ulonglong2 wA1 = *(const ulonglong2*)&WsT[c][dbase + 4];
        ulonglong2 wA2 = *(const ulonglong2*)&WsT[c][dbase + 8];
        ulonglong2 wA3 = *(const ulonglong2*)&WsT[c][dbase + 12];
        ulonglong2 wB0 = *(const ulonglong2*)&WsT[32 + c][dbase];
        ulonglong2 wB1 = *(const ulonglong2*)&WsT[32 + c][dbase + 4];
        ulonglong2 wB2 = *(const ulonglong2*)&WsT[32 + c][dbase + 8];
        ulonglong2 wB3 = *(const ulonglong2*)&WsT[32 + c][dbase + 12];
        u64 w1[8] = {wA0.x, wA0.y, wA1.x, wA1.y, wA2.x, wA2.y, wA3.x, wA3.y};
        u64 w2[8] = {wB0.x, wB0.y, wB1.x, wB1.y, wB2.x, wB2.y, wB3.x, wB3.y};
        #pragma unroll
        for (int k = 0; k < 8; k++) {
            #pragma unroll
            for (int p = 0; p < 4; p++) {
                acc[p][k] = fma2(ax[p], w1[k], acc[p][k]);
                acc[p][k] = fma2(bx[p], w2[k], acc[p][k]);
            }
        }
    }

    #pragma unroll
    for (int p = 0; p < 4; p++) {
        float* o = out + (size_t)(p0 + pg * 4 + p) * 64 + dbase;
        #pragma unroll
        for (int k = 0; k < 4; k++) {
            float2 lo = unpk(acc[p][2 * k]);
            float2 hi = unpk(acc[p][2 * k + 1]);
            *(float4*)&o[4 * k] = make_float4(lo.x, lo.y, hi.x, hi.y);
        }
    }
}

// ---------------- launch ----------------
extern "C" void kernel_launch(void* const* d_in, const int* in_sizes, int n_in,
                              void* d_out, int out_size)
{
    const float* x      = (const float*)d_in[0];
    const float* w_qkv  = (const float*)d_in[1];
    const float* b_qkv  = (const float*)d_in[2];
    const float* pos    = (const float*)d_in[3];
    const float* amp_w  = (const float*)d_in[4];
    const float* amp_b  = (const float*)d_in[5];
    const float* pha_w  = (const float*)d_in[6];
    const float* pha_b  = (const float*)d_in[7];
    const float* proj_w = (const float*)d_in[8];
    const float* proj_b = (const float*)d_in[9];
    float* out = (float*)d_out;

    transpose_pos_kernel<<<64, 256>>>(pos);
    attn_kernel<<<8192, 256>>>(x, w_qkv, b_qkv);
    rowfft_kernel<<<8192, 256>>>(x);
    coltrans_kernel<<<dim3(17, 256), 256>>>(amp_w, amp_b, pha_w, pha_b);
    rowifft_kernel<<<8192, 256>>>();
    proj_kernel<<<8192, 64>>>(proj_w, proj_b, out);
}

// round 7
// speedup vs baseline: 2.3854x; 1.0871x over previous
#include <cuda_runtime.h>
#include <cstdint>

#define PI_F 3.14159265358979323846f
typedef unsigned long long u64;

// ---------------- scratch (device globals; no runtime allocation) ----------------
__device__ float2 g_spec[256u * 256u * 129u];      // [img=b*32+ch][row][k] spectrum
__device__ float  g_x1[8u * 256u * 256u * 32u];    // [pix][32] local-mixer out
__device__ float  g_x2[256u * 256u * 256u];        // [img][row][w] global-mixer out
__device__ float  g_posT[4 * 64 * 64];             // pos transposed: [h][j][i]

// ---------------- helpers ----------------
__device__ __forceinline__ u64 fma2(u64 a, u64 b, u64 c) {
    u64 d; asm("fma.rn.f32x2 %0, %1, %2, %3;" : "=l"(d) : "l"(a), "l"(b), "l"(c)); return d;
}
__device__ __forceinline__ u64 pack2(float lo, float hi) {
    u64 r; asm("mov.b64 %0, {%1, %2};" : "=l"(r) : "f"(lo), "f"(hi)); return r;
}
__device__ __forceinline__ float2 unpk(u64 v) {
    float2 r; asm("mov.b64 {%0, %1}, %2;" : "=f"(r.x), "=f"(r.y) : "l"(v)); return r;
}
__device__ __forceinline__ float2 cmulf(float2 a, float2 b) {
    return make_float2(a.x * b.x - a.y * b.y, a.x * b.y + a.y * b.x);
}

// bank-conflict-killing swizzle for the FFT smem buffers (fixed bijection per FFT).
__device__ __forceinline__ int phy(int idx, int fx) {
    return idx ^ ((((idx) >> 4) & 3) * 5) ^ fx;
}
__device__ __forceinline__ int fxof(int f) {
    return ((f & 1) * 9) ^ (f & 2) ^ (f & 4);
}

// ---------------- pos transpose (tiny, once per launch) ----------------
__global__ __launch_bounds__(256) void transpose_pos_kernel(const float* __restrict__ pos)
{
    int idx = blockIdx.x * 256 + threadIdx.x;      // 16384 elements
    int h = idx >> 12;
    int j = (idx >> 6) & 63;
    int i = idx & 63;
    g_posT[idx] = pos[((h * 64) + i) * 64 + j];
}

// ---------------- local mixer: window attention ----------------
// one block = one 8x8 window, 256 threads. thread t -> (token i = t&63, head/quarter hq = t>>6)
__global__ __launch_bounds__(256) void attn_kernel(
    const float* __restrict__ x, const float* __restrict__ wqkv,
    const float* __restrict__ bqkv)
{
    __shared__ float xw[64][36];   // 144B rows, 16B aligned
    __shared__ float wq[96][36];
    __shared__ float bq[96];
    __shared__ float ks[64][36];
    __shared__ float vs[64][36];

    int t = threadIdx.x;
    int wid = blockIdx.x;               // 0..8191
    int b   = wid >> 10;
    int hb  = (wid >> 5) & 31;
    int wb  = wid & 31;

    // load window x1 (channels 0..31): 64 tokens x 32 floats, float4
    {
        const float4* xv = (const float4*)x;
        #pragma unroll
        for (int e = 0; e < 2; e++) {
            int l = t + e * 256;        // 0..511
            int n = l >> 3;             // token
            int q4 = l & 7;             // float4 chunk
            int i = n >> 3, j = n & 7;
            size_t pix = ((size_t)(b * 256 + hb * 8 + i) * 256) + (wb * 8 + j);
            *(float4*)&xw[n][q4 * 4] = xv[pix * 16 + q4];
        }
        #pragma unroll
        for (int e = 0; e < 12; e++) {
            int l = t + e * 256;        // 0..3071
            wq[l >> 5][l & 31] = wqkv[l];
        }
        if (t < 96) bq[t] = bqkv[t];
    }
    __syncthreads();

    int i  = t & 63;    // token
    int hq = t >> 6;    // head == qkv quarter for this thread

    // register-cache this token's row
    u64 xr[16];
    #pragma unroll
    for (int c = 0; c < 8; c++) {
        ulonglong2 v = *(const ulonglong2*)&xw[i][4 * c];
        xr[2 * c] = v.x; xr[2 * c + 1] = v.y;
    }

    // qkv for this thread's 8 channels of each of q,k,v.
    u64 q2[4];
    #pragma unroll
    for (int kind = 0; kind < 3; kind++) {
        float o[8];
        #pragma unroll
        for (int dd = 0; dd < 8; dd++) {
            int d = kind * 32 + hq * 8 + dd;
            const float* wrow = &wq[d][0];
            u64 a0 = 0ull, a1 = 0ull;
            #pragma unroll
            for (int c = 0; c < 4; c++) {
                ulonglong2 w0 = *(const ulonglong2*)(wrow + 8 * c);        // floats 8c..8c+3
                ulonglong2 w1 = *(const ulonglong2*)(wrow + 8 * c + 4);    // floats 8c+4..8c+7
                a0 = fma2(xr[4 * c],     w0.x, a0);
                a1 = fma2(xr[4 * c + 1], w0.y, a1);
                a0 = fma2(xr[4 * c + 2], w1.x, a0);
                a1 = fma2(xr[4 * c + 3], w1.y, a1);
            }
            float2 p = unpk(a0), q = unpk(a1);
            o[dd] = p.x + p.y + q.x + q.y + bq[d];
        }
        if (kind == 0) {
            #pragma unroll
            for (int c = 0; c < 4; c++)
                q2[c] = pack2(o[2 * c]     * 0.35355339059327373f,
                              o[2 * c + 1] * 0.35355339059327373f);
        } else if (kind == 1) {
            *(float4*)&ks[i][hq * 8]     = make_float4(o[0], o[1], o[2], o[3]);
            *(float4*)&ks[i][hq * 8 + 4] = make_float4(o[4], o[5], o[6], o[7]);
        } else {
            *(float4*)&vs[i][hq * 8]     = make_float4(o[0], o[1], o[2], o[3]);
            *(float4*)&vs[i][hq * 8 + 4] = make_float4(o[4], o[5], o[6], o[7]);
        }
    }
    __syncthreads();

    // attention: thread = (head hq, query row i). K/V rows uniform per warp.
    {
        const float* pT = g_posT + hq * 4096 + i;   // pT[j*64] coalesced across lanes
        float sim[64];
        float m = -1e30f;
        #pragma unroll
        for (int j = 0; j < 64; j++) {
            ulonglong2 k0 = *(const ulonglong2*)&ks[j][hq * 8];
            ulonglong2 k1 = *(const ulonglong2*)&ks[j][hq * 8 + 4];
            u64 a = 0ull;
            a = fma2(q2[0], k0.x, a);
            a = fma2(q2[1], k0.y, a);
            a = fma2(q2[2], k1.x, a);
            a = fma2(q2[3], k1.y, a);
            float2 p = unpk(a);
            float s = p.x + p.y + pT[j * 64];
            sim[j] = s;
            m = fmaxf(m, s);
        }
        float sum = 0.f;
        #pragma unroll
        for (int j = 0; j < 64; j++) {
            float e = __expf(sim[j] - m);
            sim[j] = e; sum += e;
        }
        float inv = 1.f / sum;
        u64 o2[4] = {0ull, 0ull, 0ull, 0ull};
        #pragma unroll
        for (int j = 0; j < 64; j++) {
            ulonglong2 v0 = *(const ulonglong2*)&vs[j][hq * 8];
            ulonglong2 v1 = *(const ulonglong2*)&vs[j][hq * 8 + 4];
            u64 pb = pack2(sim[j], sim[j]);
            o2[0] = fma2(pb, v0.x, o2[0]);
            o2[1] = fma2(pb, v0.y, o2[1]);
            o2[2] = fma2(pb, v1.x, o2[2]);
            o2[3] = fma2(pb, v1.y, o2[3]);
        }
        float2 r0 = unpk(o2[0]), r1 = unpk(o2[1]), r2 = unpk(o2[2]), r3 = unpk(o2[3]);
        int ir = i >> 3, jc = i & 7;
        size_t pix = ((size_t)(b * 256 + hb * 8 + ir) * 256) + (wb * 8 + jc);
        float4* op = (float4*)(g_x1 + pix * 32 + hq * 8);
        op[0] = make_float4(r0.x * inv, r0.y * inv, r1.x * inv, r1.y * inv);
        op[1] = make_float4(r2.x * inv, r2.y * inv, r3.x * inv, r3.y * inv);
    }
}

// ---------------- 8 parallel 256-pt Stockham radix-4 FFTs in smem (swizzled) ----
// all 256 threads must call. 4 stages -> result back in bufA. All buffer indices
// are PHYSICAL (phy-swizzled); callers must use phy() too.
template <int SIGN>
__device__ __forceinline__ float2* fft8x256_r4(float2* bufA, float2* bufB, int t)
{
    float2* in = bufA; float2* out = bufB;
    #pragma unroll
    for (int Ns = 1; Ns < 256; Ns <<= 2) {
        float fac = (float)SIGN * (PI_F * 0.5f) / (float)Ns;  // 2*pi/(4*Ns)
        #pragma unroll
        for (int s = 0; s < 2; s++) {
            int m = t + s * 256;           // 0..511 butterflies
            int f = m >> 6;                // which FFT
            int fb = f * 256;
            int fx = fxof(f);
            int j = m & 63;
            float2 v0 = in[fb + phy(j,       fx)];
            float2 v1 = in[fb + phy(j + 64,  fx)];
            float2 v2 = in[fb + phy(j + 128, fx)];
            float2 v3 = in[fb + phy(j + 192, fx)];
            int r = j & (Ns - 1);
            float ang = fac * (float)r;
            float sn, cs; __sincosf(ang, &sn, &cs);
            float2 w1 = make_float2(cs, sn);
            float2 w2 = cmulf(w1, w1);
            float2 w3 = cmulf(w2, w1);
            v1 = cmulf(v1, w1);
            v2 = cmulf(v2, w2);
            v3 = cmulf(v3, w3);
            float2 t0 = make_float2(v0.x + v2.x, v0.y + v2.y);
            float2 t1 = make_float2(v0.x - v2.x, v0.y - v2.y);
            float2 t2 = make_float2(v1.x + v3.x, v1.y + v3.y);
            float2 t3 = make_float2(v1.x - v3.x, v1.y - v3.y);
            float sx = (float)SIGN * t3.x;
            float sy = (float)SIGN * t3.y;
            int idxD = ((j - r) << 2) + r;   // (j/Ns)*4Ns + r
            out[fb + phy(idxD,          fx)] = make_float2(t0.x + t2.x, t0.y + t2.y);
            out[fb + phy(idxD + Ns,     fx)] = make_float2(t1.x - sy,   t1.y + sx);
            out[fb + phy(idxD + 2 * Ns, fx)] = make_float2(t0.x - t2.x, t0.y - t2.y);
            out[fb + phy(idxD + 3 * Ns, fx)] = make_float2(t1.x + sy,   t1.y - sx);
        }
        __syncthreads();
        float2* tmp = in; in = out; out = tmp;
    }
    return in;  // 4 stages -> bufA
}

// ---------------- forward row rFFT (along w), 2 real channels per complex FFT ---
// block = (b, row, channel-group of 16); 4096 blocks, 256 threads
__global__ __launch_bounds__(256, 4) void rowfft_kernel(const float* __restrict__ x)
{
    __shared__ float2 bufA[8 * 256];
    __shared__ float2 bufB[8 * 256];
    int t  = threadIdx.x;
    int bx = blockIdx.x;
    int b   = bx >> 9;              // 8
    int row = (bx >> 1) & 255;
    int g   = bx & 1;               // 2 groups of 16 channels

    // FFT f packs channels (32 + g*16 + 2f) as real, (+1) as imag: one float2 load.
    const float* xp = x + ((size_t)(b * 256 + row) * 256) * 64 + 32 + g * 16;
    #pragma unroll
    for (int e = 0; e < 8; e++) {
        int l = t + e * 256;        // 0..2047
        int w = l >> 3;
        int f = l & 7;
        bufA[f * 256 + phy(w, fxof(f))] = *(const float2*)(xp + (size_t)w * 64 + 2 * f);
    }
    __syncthreads();

    float2* res = fft8x256_r4<-1>(bufA, bufB, t);

    int img0 = b * 32 + g * 16;
    if (t < 129) {
        int m = (256 - t) & 255;
        #pragma unroll
        for (int f = 0; f < 8; f++) {
            int fx = fxof(f);
            float2 zk = res[f * 256 + phy(t, fx)];
            float2 zm = res[f * 256 + phy(m, fx)];
            // A = even channel spectrum, B = odd channel spectrum
            float2 A  = make_float2(0.5f * (zk.x + zm.x), 0.5f * (zk.y - zm.y));
            float2 Bv = make_float2(0.5f * (zk.y + zm.y), 0.5f * (zm.x - zk.x));
            size_t o = ((size_t)(img0 + 2 * f) * 256 + row) * 129 + t;
            g_spec[o] = A;
            g_spec[o + (size_t)256 * 129] = Bv;
        }
    }
}

// ---------------- column FFT (along h) + amp/phase transform + column IFFT ------
// block = (k-group of 8, img); grid (17, 256), 256 threads
__global__ __launch_bounds__(256, 4) void coltrans_kernel(
    const float* __restrict__ amp_w, const float* __restrict__ amp_b,
    const float* __restrict__ pha_w, const float* __restrict__ pha_b)
{
    __shared__ float2 bufA[8 * 256];
    __shared__ float2 bufB[8 * 256];
    int t   = threadIdx.x;
    int img = blockIdx.y;
    int k0  = blockIdx.x * 8;
    int ch  = img & 31;

    float aw = amp_w[ch], ab = amp_b[ch], pw = pha_w[ch], pb = pha_b[ch];

    size_t base = (size_t)img * 256 * 129;
    #pragma unroll
    for (int e = 0; e < 8; e++) {
        int l = t + e * 256;
        int row = l >> 3;
        int kk  = l & 7;
        int k   = k0 + kk;
        float2 v = make_float2(0.f, 0.f);
        if (k < 129) v = g_spec[base + (size_t)row * 129 + k];
        bufA[kk * 256 + phy(row, fxof(kk))] = v;
    }
    __syncthreads();

    float2* mid = fft8x256_r4<-1>(bufA, bufB, t);   // forward along h

    // elementwise amp/phase affine (order-agnostic: operate on physical slots)
    #pragma unroll
    for (int e = 0; e < 8; e++) {
        int idx = t + e * 256;
        float2 v = mid[idx];
        float amp = sqrtf(v.x * v.x + v.y * v.y);
        float pha = atan2f(v.y, v.x);
        float af = amp * aw + ab;
        float pf = pha * pw + pb;
        float sn, cs; __sincosf(pf, &sn, &cs);
        mid[idx] = make_float2(af * cs + 2e-8f, af * sn + 1e-8f);
    }
    __syncthreads();

    float2* res = fft8x256_r4<1>(bufA, bufB, t);    // inverse along h (unscaled)

    #pragma unroll
    for (int e = 0; e < 8; e++) {
        int l = t + e * 256;
        int row = l >> 3;
        int kk  = l & 7;
        int k   = k0 + kk;
        if (k < 129) g_spec[base + (size_t)row * 129 + k] = res[kk * 256 + phy(row, fxof(kk))];
    }
}

// ---------------- inverse row irFFT (along w) + abs, 2 image planes per FFT -----
// irfft semantics: Im at k=0 and k=128 is DISCARDED -> zero it so the packed
// Hermitian extension is exact. block = (img-pair, row-group of 8); 4096 blocks.
__global__ __launch_bounds__(256, 4) void rowifft_kernel()
{
    __shared__ float2 bufA[8 * 256];
    __shared__ float2 bufB[8 * 256];
    int t  = threadIdx.x;
    int bx = blockIdx.x;
    int p    = bx >> 5;             // img pair 0..127
    int row0 = (bx & 31) * 8;
    int imgA = 2 * p;

    size_t baseA = ((size_t)imgA * 256 + row0) * 129;
    size_t baseB = baseA + (size_t)256 * 129;
    if (t < 129) {
        bool edge = (t == 0) || (t == 128);
        #pragma unroll
        for (int f = 0; f < 8; f++) {
            int fx = fxof(f);
            float2 A  = g_spec[baseA + (size_t)f * 129 + t];
            float2 Bv = g_spec[baseB + (size_t)f * 129 + t];
            if (edge) { A.y = 0.f; Bv.y = 0.f; }   // irfft discards Im at DC/Nyquist
            // Z[t] = A + iB  (t <= 128)
            bufA[f * 256 + phy(t, fx)] = make_float2(A.x - Bv.y, A.y + Bv.x);
            // Z[256-t] = conj(A) + i*conj(B)  (1 <= t <= 127)
            if (t >= 1 && t < 128)
                bufA[f * 256 + phy(256 - t, fx)] = make_float2(A.x + Bv.y, Bv.x - A.y);
        }
    }
    __syncthreads();

    float2* res = fft8x256_r4<1>(bufA, bufB, t);

    #pragma unroll
    for (int e = 0; e < 8; e++) {
        int l = t + e * 256;
        int f = l >> 8;
        int n = l & 255;
        float2 v = res[f * 256 + phy(n, fxof(f))];
        size_t oA = ((size_t)imgA * 256 + row0 + f) * 256 + n;
        g_x2[oA]         = fabsf(v.x * (1.f / 65536.f));   // even img plane
        g_x2[oA + 65536] = fabsf(v.y * (1.f / 65536.f));   // odd img plane
    }
}

// ---------------- projection: out = [x1|x2] @ proj_w^T + proj_b ----------------
// block = 64 pixels, 64 threads; thread = 4 pixels x 16 output channels, f32x2
__global__ __launch_bounds__(64) void proj_kernel(
    const float* __restrict__ pw, const float* __restrict__ pbias,
    float* __restrict__ out)
{
    __shared__ float WsT[64][68];    // transposed weights: [in c][out d]
    __shared__ float x1s[32][68];    // [c][pi]
    __shared__ float x2s[32][68];    // [c][pi]
    int t  = threadIdx.x;
    int p0 = blockIdx.x * 64;
    int b    = p0 >> 16;
    int rem0 = p0 & 65535;

    #pragma unroll
    for (int e = 0; e < 64; e++) WsT[t][e] = pw[e * 64 + t];     // coalesced reads
    #pragma unroll
    for (int e = 0; e < 32; e++) {
        int l = e * 64 + t;                  // 0..2047, coalesced read of g_x1
        x1s[l & 31][l >> 5] = g_x1[(size_t)p0 * 32 + l];
    }
    {
        size_t xb = (size_t)b * 2097152 + rem0;
        #pragma unroll
        for (int e = 0; e < 32; e++)
            x2s[e][t] = g_x2[xb + (size_t)e * 65536 + t];        // coalesced per channel
    }
    __syncthreads();

    int pg    = t >> 2;            // pixel group: pixels pg*4 .. pg*4+3
    int dbase = (t & 3) << 4;      // 0,16,32,48
    u64 acc[4][8];                 // [pixel][d-pair]
    #pragma unroll
    for (int k = 0; k < 8; k++) {
        u64 bp = *(const u64*)&pbias[dbase + 2 * k];
        #pragma unroll
        for (int p = 0; p < 4; p++) acc[p][k] = bp;
    }

    #pragma unroll
    for (int c = 0; c < 32; c++) {
        float4 a  = *(const float4*)&x1s[c][pg * 4];
        float4 b2 = *(const float4*)&x2s[c][pg * 4];
        u64 ax[4] = {pack2(a.x, a.x),   pack2(a.y, a.y),   pack2(a.z, a.z),   pack2(a.w, a.w)};
        u64 bx[4] = {pack2(b2.x, b2.x), pack2(b2.y, b2.y), pack2(b2.z, b2.z), pack2(b2.w, b2.w)};
        // weights via broadcast LDS.128 (uniform within lane-quad)
        ulonglong2 wA0 = *(const ulonglong2*)&WsT[c][dbase];
        ulonglong2 wA1 = *(const ulonglong2*)&WsT[c][dbase + 4];
        ulonglong2 wA2 = *(const ulonglong2*)&WsT[c][dbase + 8];
        ulonglong2 wA3 = *(const ulonglong2*)&WsT[c][dbase + 12];
        ulonglong2 wB0 = *(const ulonglong2*)&WsT[32 + c][dbase];
        ulonglong2 wB1 = *(const ulonglong2*)&WsT[32 + c][dbase + 4];
        ulonglong2 wB2 = *(const ulonglong2*)&WsT[32 + c][dbase + 8];
        ulonglong2 wB3 = *(const ulonglong2*)&WsT[32 + c][dbase + 12];
        u64 w1[8] = {wA0.x, wA0.y, wA1.x, wA1.y, wA2.x, wA2.y, wA3.x, wA3.y};
        u64 w2[8] = {wB0.x, wB0.y, wB1.x, wB1.y, wB2.x, wB2.y, wB3.x, wB3.y};
        #pragma unroll
        for (int k = 0; k < 8; k++) {
            #pragma unroll
            for (int p = 0; p < 4; p++) {
                acc[p][k] = fma2(ax[p], w1[k], acc[p][k]);
                acc[p][k] = fma2(bx[p], w2[k], acc[p][k]);
            }
        }
    }

    #pragma unroll
    for (int p = 0; p < 4; p++) {
        float* o = out + (size_t)(p0 + pg * 4 + p) * 64 + dbase;
        #pragma unroll
        for (int k = 0; k < 4; k++) {
            float2 lo = unpk(acc[p][2 * k]);
            float2 hi = unpk(acc[p][2 * k + 1]);
            *(float4*)&o[4 * k] = make_float4(lo.x, lo.y, hi.x, hi.y);
        }
    }
}

// ---------------- launch ----------------
extern "C" void kernel_launch(void* const* d_in, const int* in_sizes, int n_in,
                              void* d_out, int out_size)
{
    const float* x      = (const float*)d_in[0];
    const float* w_qkv  = (const float*)d_in[1];
    const float* b_qkv  = (const float*)d_in[2];
    const float* pos    = (const float*)d_in[3];
    const float* amp_w  = (const float*)d_in[4];
    const float* amp_b  = (const float*)d_in[5];
    const float* pha_w  = (const float*)d_in[6];
    const float* pha_b  = (const float*)d_in[7];
    const float* proj_w = (const float*)d_in[8];
    const float* proj_b = (const float*)d_in[9];
    float* out = (float*)d_out;

    transpose_pos_kernel<<<64, 256>>>(pos);
    attn_kernel<<<8192, 256>>>(x, w_qkv, b_qkv);
    rowfft_kernel<<<4096, 256>>>(x);
    coltrans_kernel<<<dim3(17, 256), 256>>>(amp_w, amp_b, pha_w, pha_b);
    rowifft_kernel<<<4096, 256>>>();
    proj_kernel<<<8192, 64>>>(proj_w, proj_b, out);
}